// round 5
// baseline (speedup 1.0000x reference)
#include <cuda_runtime.h>
#include <math.h>

static constexpr int V   = 32000;    // vocab (row length)
static constexpr int V4  = V / 4;    // float4 count per row
static constexpr int NT  = 512;      // threads per CTA
static constexpr int NW  = NT / 32;  // warps per CTA

__global__ void __launch_bounds__(NT)
bisection_loss_kernel(const float* __restrict__ X,
                      const int* __restrict__ target_raw,   // int32 OR int64 (detected)
                      float* __restrict__ out)
{
    __shared__ float r1[NW];
    __shared__ float r2[NW];
    __shared__ float r3[NW];
    __shared__ float sb;   // broadcast t_f

    const int tid  = threadIdx.x;
    const int lane = tid & 31;
    const int wid  = tid >> 5;
    const long long row = blockIdx.x;

    const float* __restrict__ xrow = X + row * (long long)V;
    const float4* __restrict__ g4  = reinterpret_cast<const float4*>(xrow);

    // ---- Pass 1: stream row, track per-thread top-2 of Xs = 0.5*X ----
    float m1 = -INFINITY, m2 = -INFINITY;
    for (int i = tid; i < V4; i += NT) {
        float4 v = __ldg(&g4[i]);
        float a;
        a = 0.5f * v.x; if (a > m1) { m2 = m1; m1 = a; } else if (a > m2) m2 = a;
        a = 0.5f * v.y; if (a > m1) { m2 = m1; m1 = a; } else if (a > m2) m2 = a;
        a = 0.5f * v.z; if (a > m1) { m2 = m1; m1 = a; } else if (a > m2) m2 = a;
        a = 0.5f * v.w; if (a > m1) { m2 = m1; m1 = a; } else if (a > m2) m2 = a;
    }
    // warp-level top-2 merge
    #pragma unroll
    for (int off = 16; off; off >>= 1) {
        float o1 = __shfl_down_sync(0xffffffffu, m1, off);
        float o2 = __shfl_down_sync(0xffffffffu, m2, off);
        if (o1 > m1) { m2 = fmaxf(m1, o2); m1 = o1; }
        else         { m2 = fmaxf(m2, o1); }
    }
    if (lane == 0) { r1[wid] = m1; r2[wid] = m2; }
    __syncthreads();

    // ---- Scalar bisection (thread 0): exact f32 replication of reference ----
    if (tid == 0) {
        float M1 = r1[0], M2 = r2[0];
        #pragma unroll
        for (int w = 1; w < NW; w++) {
            float o1 = r1[w], o2 = r2[w];
            if (o1 > M1) { M2 = fmaxf(M1, o2); M1 = o1; }
            else         { M2 = fmaxf(M2, o1); }
        }
        const float CEXP = (float)(1.0 / 31999.0);         // inv_exp as f32
        float tmin = M1 - 1.0f;
        float tmax = M1 - (float)0.005590169943749474;     // d^(1-alpha) in f32
        float diff = tmax - tmin;
        float t    = tmin;
        #pragma unroll 1
        for (int it = 0; it < 50; it++) {
            diff *= 0.5f;
            t = tmin + diff;
            bool mask;
            if (M2 > t) {
                // >=2 elements above t: each z in (0.9967,1) -> sum >= 1.99 >= 1
                mask = true;
            } else {
                // only the max is above t: sum = powf(M1 - t, c)
                float y = M1 - t;                          // t < tmax < M1 always
                mask = (powf(y, CEXP) - 1.0f >= 0.0f);
            }
            if (mask) tmin = t;
        }
        sb = t;   // final Z uses the LAST iteration's t (not t_min)
    }
    __syncthreads();
    const float tf = sb;

    // ---- Pass 2: reread row (L2-resident), accumulate S, A=sum z^1.5, D=sum z*X ----
    const float CEXP = (float)(1.0 / 31999.0);
    float S = 0.0f, A = 0.0f, D = 0.0f;
    for (int i = tid; i < V4; i += NT) {
        float4 v = __ldg(&g4[i]);
        float y;
        y = 0.5f * v.x - tf;
        if (y > 0.0f) { float z = powf(y, CEXP); S += z; A += z * sqrtf(z); D += z * v.x; }
        y = 0.5f * v.y - tf;
        if (y > 0.0f) { float z = powf(y, CEXP); S += z; A += z * sqrtf(z); D += z * v.y; }
        y = 0.5f * v.z - tf;
        if (y > 0.0f) { float z = powf(y, CEXP); S += z; A += z * sqrtf(z); D += z * v.z; }
        y = 0.5f * v.w - tf;
        if (y > 0.0f) { float z = powf(y, CEXP); S += z; A += z * sqrtf(z); D += z * v.w; }
    }
    #pragma unroll
    for (int off = 16; off; off >>= 1) {
        S += __shfl_down_sync(0xffffffffu, S, off);
        A += __shfl_down_sync(0xffffffffu, A, off);
        D += __shfl_down_sync(0xffffffffu, D, off);
    }
    if (lane == 0) { r1[wid] = S; r2[wid] = A; r3[wid] = D; }
    __syncthreads();

    if (tid == 0) {
        float Ss = 0.0f, As = 0.0f, Ds = 0.0f;
        #pragma unroll
        for (int w = 0; w < NW; w++) { Ss += r1[w]; As += r2[w]; Ds += r3[w]; }

        // ---- dtype-agnostic target fetch (int32 vs int64 buffer) ----
        // int64 little-endian with values in [0,32000) => every odd 32-bit
        // word of the buffer is 0. Genuine int32 targets have ~0 chance of
        // 32 consecutive odd-position zeros.
        bool is_i64 = true;
        #pragma unroll 1
        for (int k = 1; k < 64; k += 2) {
            if (__ldg(&target_raw[k]) != 0) { is_i64 = false; break; }
        }
        int tg;
        if (is_i64) tg = __ldg(&target_raw[2 * (int)row]);   // low word of int64
        else        tg = __ldg(&target_raw[(int)row]);
        if (tg < 0) tg = 0;
        if (tg >= V) tg = V - 1;   // defensive clamp: never fault

        float xt = __ldg(&xrow[tg]);
        // sum(p^alpha) = A / S^1.5 ; loss = (1 - sumPa)/0.75 + D/S - X[target]
        float sumPa = As / (Ss * sqrtf(Ss));
        out[row] = (1.0f - sumPa) / 0.75f + Ds / Ss - xt;
    }
}

extern "C" void kernel_launch(void* const* d_in, const int* in_sizes, int n_in,
                              void* d_out, int out_size)
{
    const float* X   = (const float*)d_in[0];
    const int*   tgt = (const int*)d_in[1];
    float*       out = (float*)d_out;
    const int B = out_size;   // 4096 rows

    bisection_loss_kernel<<<B, NT>>>(X, tgt, out);
}

// round 6
// speedup vs baseline: 1.1423x; 1.1423x over previous
#include <cuda_runtime.h>
#include <math.h>

static constexpr int V   = 32000;    // vocab (row length)
static constexpr int V4  = V / 4;    // float4 count per row
static constexpr int NT  = 512;      // threads per CTA
static constexpr int NW  = NT / 32;  // warps per CTA

__global__ void __launch_bounds__(NT)
bisection_loss_kernel(const float* __restrict__ X,
                      const int* __restrict__ target_raw,   // int32 OR int64 (detected)
                      float* __restrict__ out)
{
    __shared__ float r1[NW];
    __shared__ float r2[NW];
    __shared__ float r3[NW];

    const int tid  = threadIdx.x;
    const int lane = tid & 31;
    const int wid  = tid >> 5;
    const long long row = blockIdx.x;

    const float* __restrict__ xrow = X + row * (long long)V;
    const float4* __restrict__ g4  = reinterpret_cast<const float4*>(xrow);

    // ---- Pass 1: per-thread MAX only (1 FMNMX/elem), raw X (no 0.5 scale) ----
    float lmax = -INFINITY;
    #pragma unroll 4
    for (int i = tid; i < V4; i += NT) {
        float4 v = __ldg(&g4[i]);
        lmax = fmaxf(lmax, fmaxf(fmaxf(v.x, v.y), fmaxf(v.z, v.w)));
    }
    // block max -> M1 (all threads)
    float wm = lmax;
    #pragma unroll
    for (int off = 16; off; off >>= 1)
        wm = fmaxf(wm, __shfl_xor_sync(0xffffffffu, wm, off));
    if (lane == 0) r1[wid] = wm;
    __syncthreads();
    float M1 = r1[0];
    #pragma unroll
    for (int w = 1; w < NW; w++) M1 = fmaxf(M1, r1[w]);

    // ---- Second max: winner-thread rescan (handles cross-thread dups) ----
    int nwin = __syncthreads_count(lmax == M1);   // #threads whose local max == M1
    float M2;
    if (nwin >= 2) {
        M2 = M1;                                   // M1 occurs in >=2 distinct elements
    } else {
        float cand = lmax;                         // losers contribute their max
        if (lmax == M1) {
            // winner: local top-2 rescan of its own ~64 elements (L2 hits)
            float a1 = -INFINITY, a2 = -INFINITY;
            #pragma unroll 4
            for (int i = tid; i < V4; i += NT) {
                float4 v = __ldg(&g4[i]);
                float a;
                a = v.x; if (a > a1) { a2 = a1; a1 = a; } else if (a > a2) a2 = a;
                a = v.y; if (a > a1) { a2 = a1; a1 = a; } else if (a > a2) a2 = a;
                a = v.z; if (a > a1) { a2 = a1; a1 = a; } else if (a > a2) a2 = a;
                a = v.w; if (a > a1) { a2 = a1; a1 = a; } else if (a > a2) a2 = a;
            }
            cand = a2;
        }
        float wc = cand;
        #pragma unroll
        for (int off = 16; off; off >>= 1)
            wc = fmaxf(wc, __shfl_xor_sync(0xffffffffu, wc, off));
        if (lane == 0) r2[wid] = wc;
        __syncthreads();
        M2 = r2[0];
        #pragma unroll
        for (int w = 1; w < NW; w++) M2 = fmaxf(M2, r2[w]);
    }

    // ---- Bisection (all threads redundantly), exact f32 replication ----
    const float CEXP = (float)(1.0 / 31999.0);         // inv_exp as f32
    const float M1s = 0.5f * M1;                        // Xs = (alpha-1)*X, exact
    const float M2s = 0.5f * M2;
    float tmin = M1s - 1.0f;
    float tmax = M1s - (float)0.005590169943749474;     // d^(1-alpha) in f32
    float diff = tmax - tmin;
    float t    = tmin;
    if (M1s - M2s < 0.98f) {
        // powf branch provably < 1 for all reachable y -> mask == (M2s > t)
        #pragma unroll 1
        for (int it = 0; it < 50; it++) {
            diff *= 0.5f;
            t = tmin + diff;
            if (M2s > t) tmin = t;
        }
    } else {
        #pragma unroll 1
        for (int it = 0; it < 50; it++) {
            diff *= 0.5f;
            t = tmin + diff;
            bool mask = (M2s > t) || (powf(M1s - t, CEXP) - 1.0f >= 0.0f);
            if (mask) tmin = t;
        }
    }
    const float tf  = t;            // final Z uses LAST iteration's t
    const float tf2 = 2.0f * tf;    // threshold in raw-X units (exact scaling)

    // ---- Pass 2: float4 skip-test; rare slow path does the powf work ----
    float S = 0.0f, A = 0.0f, D = 0.0f;
    #pragma unroll 4
    for (int i = tid; i < V4; i += NT) {
        float4 v = __ldg(&g4[i]);
        float vm = fmaxf(fmaxf(v.x, v.y), fmaxf(v.z, v.w));
        if (vm > tf2) {   // rare: some component has y = 0.5*x - tf > 0
            float y;
            y = 0.5f * v.x - tf;
            if (y > 0.0f) { float z = powf(y, CEXP); S += z; A += z * sqrtf(z); D += z * v.x; }
            y = 0.5f * v.y - tf;
            if (y > 0.0f) { float z = powf(y, CEXP); S += z; A += z * sqrtf(z); D += z * v.y; }
            y = 0.5f * v.z - tf;
            if (y > 0.0f) { float z = powf(y, CEXP); S += z; A += z * sqrtf(z); D += z * v.z; }
            y = 0.5f * v.w - tf;
            if (y > 0.0f) { float z = powf(y, CEXP); S += z; A += z * sqrtf(z); D += z * v.w; }
        }
    }
    #pragma unroll
    for (int off = 16; off; off >>= 1) {
        S += __shfl_down_sync(0xffffffffu, S, off);
        A += __shfl_down_sync(0xffffffffu, A, off);
        D += __shfl_down_sync(0xffffffffu, D, off);
    }
    __syncthreads();   // protect r1..r3 reuse
    if (lane == 0) { r1[wid] = S; r2[wid] = A; r3[wid] = D; }
    __syncthreads();

    if (tid == 0) {
        float Ss = 0.0f, As = 0.0f, Ds = 0.0f;
        #pragma unroll
        for (int w = 0; w < NW; w++) { Ss += r1[w]; As += r2[w]; Ds += r3[w]; }

        // ---- dtype-agnostic target fetch (int32 vs int64 buffer) ----
        bool is_i64 = true;
        #pragma unroll 1
        for (int k = 1; k < 64; k += 2) {
            if (__ldg(&target_raw[k]) != 0) { is_i64 = false; break; }
        }
        int tg;
        if (is_i64) tg = __ldg(&target_raw[2 * (int)row]);   // low word of int64
        else        tg = __ldg(&target_raw[(int)row]);
        if (tg < 0) tg = 0;
        if (tg >= V) tg = V - 1;   // defensive clamp: never fault

        float xt = __ldg(&xrow[tg]);
        // sum(p^alpha) = A / S^1.5 ; loss = (1 - sumPa)/0.75 + D/S - X[target]
        float sumPa = As / (Ss * sqrtf(Ss));
        out[row] = (1.0f - sumPa) / 0.75f + Ds / Ss - xt;
    }
}

extern "C" void kernel_launch(void* const* d_in, const int* in_sizes, int n_in,
                              void* d_out, int out_size)
{
    const float* X   = (const float*)d_in[0];
    const int*   tgt = (const int*)d_in[1];
    float*       out = (float*)d_out;
    const int B = out_size;   // 4096 rows

    bisection_loss_kernel<<<B, NT>>>(X, tgt, out);
}

// round 8
// speedup vs baseline: 1.4806x; 1.2962x over previous
#include <cuda_runtime.h>
#include <math.h>

static constexpr int V   = 32000;    // vocab (row length)
static constexpr int V4  = V / 4;    // float4 count per row
static constexpr int NT  = 512;      // threads per CTA
static constexpr int NW  = NT / 32;  // warps per CTA

__global__ void __launch_bounds__(NT, 4)
bisection_loss_kernel(const float* __restrict__ X,
                      const int* __restrict__ target_raw,   // int32 OR int64 (detected)
                      float* __restrict__ out)
{
    __shared__ float r1[NW];
    __shared__ float r2[NW];
    __shared__ float r3[NW];

    const int tid  = threadIdx.x;
    const int lane = tid & 31;
    const int wid  = tid >> 5;
    const long long row = blockIdx.x;

    const float* __restrict__ xrow = X + row * (long long)V;
    const float4* __restrict__ g4  = reinterpret_cast<const float4*>(xrow);

    // ---- Single pass: per-thread TOP-3 (branchless, 5 FMNMX/elem) ----
    float p1 = -INFINITY, p2 = -INFINITY, p3 = -INFINITY;
    #pragma unroll 4
    for (int i = tid; i < V4; i += NT) {
        float4 v = __ldg(&g4[i]);
        float a, t2, t3;
        a = v.x; t2 = fminf(p1, a); p1 = fmaxf(p1, a);
                 t3 = fminf(p2, t2); p2 = fmaxf(p2, t2); p3 = fmaxf(p3, t3);
        a = v.y; t2 = fminf(p1, a); p1 = fmaxf(p1, a);
                 t3 = fminf(p2, t2); p2 = fmaxf(p2, t2); p3 = fmaxf(p3, t3);
        a = v.z; t2 = fminf(p1, a); p1 = fmaxf(p1, a);
                 t3 = fminf(p2, t2); p2 = fmaxf(p2, t2); p3 = fmaxf(p3, t3);
        a = v.w; t2 = fminf(p1, a); p1 = fmaxf(p1, a);
                 t3 = fminf(p2, t2); p2 = fmaxf(p2, t2); p3 = fmaxf(p3, t3);
    }

    // ---- warp top-3 merge via selection identity:
    //      m_k = max_{i+j=k+1} min(a_i, b_j)  (sorted descending, a0=b0=+inf)
    float w1 = p1, w2 = p2, w3 = p3;
    #pragma unroll
    for (int off = 16; off; off >>= 1) {
        float o1 = __shfl_xor_sync(0xffffffffu, w1, off);
        float o2 = __shfl_xor_sync(0xffffffffu, w2, off);
        float o3 = __shfl_xor_sync(0xffffffffu, w3, off);
        float n1 = fmaxf(w1, o1);
        float n2 = fmaxf(fminf(w1, o1), fmaxf(w2, o2));
        float n3 = fmaxf(fmaxf(w3, o3), fmaxf(fminf(w1, o2), fminf(w2, o1)));
        w1 = n1; w2 = n2; w3 = n3;
    }
    if (lane == 0) { r1[wid] = w1; r2[wid] = w2; r3[wid] = w3; }
    __syncthreads();
    // redundant cross-warp merge in every thread -> uniform M1 >= M2 >= M3
    float M1 = r1[0], M2 = r2[0], M3 = r3[0];
    #pragma unroll
    for (int w = 1; w < NW; w++) {
        float o1 = r1[w], o2 = r2[w], o3 = r3[w];
        float n1 = fmaxf(M1, o1);
        float n2 = fmaxf(fminf(M1, o1), fmaxf(M2, o2));
        float n3 = fmaxf(fmaxf(M3, o3), fmaxf(fminf(M1, o2), fminf(M2, o1)));
        M1 = n1; M2 = n2; M3 = n3;
    }

    // ---- multiplicities from the 3 per-thread slots.
    //      Counts can only UNDERcount (hidden 4th copy in one thread), and any
    //      undercount scenario forces the count away from 1 -> the !=1 test is
    //      a conservative fallback trigger.  (barrier-counts also sync r1..r3 reuse)
    int c1 = __syncthreads_count(p1 == M1) + __syncthreads_count(p2 == M1)
           + __syncthreads_count(p3 == M1);
    int cW = __syncthreads_count(p1 == M2) + __syncthreads_count(p2 == M2)
           + __syncthreads_count(p3 == M2);

    // ---- Bisection (all threads redundantly), exact f32 replication ----
    const float CEXP = (float)(1.0 / 31999.0);          // inv_exp as f32
    const float M1s = 0.5f * M1;                         // Xs = (alpha-1)*X, exact
    const float M2s = 0.5f * M2;
    const float M3s = 0.5f * M3;
    float tmin = M1s - 1.0f;
    float diff = (M1s - (float)0.005590169943749474) - tmin;  // tmax - tmin
    float t    = tmin;
    if (M1s - M2s < 0.98f) {
        // whenever only M1 is above t, y = M1s - t < 0.98 -> powf(y,c) provably < 1;
        // the mask reduces exactly to (M2s > t)
        #pragma unroll 1
        for (int it = 0; it < 50; it++) {
            diff *= 0.5f;
            t = tmin + diff;
            if (M2s > t) tmin = t;
        }
    } else {
        #pragma unroll 1
        for (int it = 0; it < 50; it++) {
            diff *= 0.5f;
            t = tmin + diff;
            if ((M2s > t) || (powf(M1s - t, CEXP) >= 1.0f)) tmin = t;
        }
    }
    const float tf = t;               // final Z uses the LAST iteration's t
    const bool needW = (M2s > tf);    // does the 2nd value contribute?

    // closed form is PROVABLY exact when: M1 unique, M2 unique, and no third
    // element exceeds tf (M3 is the global 3rd largest -> M3s <= tf bounds all others)
    const bool fallback = (c1 != 1) || (cW != 1) || (M3s > tf);

    float S = 0.0f, A = 0.0f, D = 0.0f;
    if (fallback) {
        // ---- rare exact path: rescan row (L2-resident), float4 skip test ----
        const float tf2 = 2.0f * tf;
        float s = 0.0f, a = 0.0f, d = 0.0f;
        #pragma unroll 2
        for (int i = tid; i < V4; i += NT) {
            float4 v = __ldg(&g4[i]);
            float vm = fmaxf(fmaxf(v.x, v.y), fmaxf(v.z, v.w));
            if (vm > tf2) {
                float y;
                y = 0.5f * v.x - tf;
                if (y > 0.0f) { float z = powf(y, CEXP); s += z; a += z * sqrtf(z); d += z * v.x; }
                y = 0.5f * v.y - tf;
                if (y > 0.0f) { float z = powf(y, CEXP); s += z; a += z * sqrtf(z); d += z * v.y; }
                y = 0.5f * v.z - tf;
                if (y > 0.0f) { float z = powf(y, CEXP); s += z; a += z * sqrtf(z); d += z * v.z; }
                y = 0.5f * v.w - tf;
                if (y > 0.0f) { float z = powf(y, CEXP); s += z; a += z * sqrtf(z); d += z * v.w; }
            }
        }
        #pragma unroll
        for (int off = 16; off; off >>= 1) {
            s += __shfl_down_sync(0xffffffffu, s, off);
            a += __shfl_down_sync(0xffffffffu, a, off);
            d += __shfl_down_sync(0xffffffffu, d, off);
        }
        __syncthreads();
        if (lane == 0) { r1[wid] = s; r2[wid] = a; r3[wid] = d; }
        __syncthreads();
        if (tid == 0) {
            #pragma unroll
            for (int w = 0; w < NW; w++) { S += r1[w]; A += r2[w]; D += r3[w]; }
        }
    } else if (tid == 0) {
        // ---- closed form: contributors are exactly {M1} (+ {M2} if needW) ----
        float z1 = powf(M1s - tf, CEXP);
        S = z1; A = z1 * sqrtf(z1); D = z1 * M1;
        if (needW) {
            float z2 = powf(M2s - tf, CEXP);
            S += z2; A += z2 * sqrtf(z2); D += z2 * M2;
        }
    }

    if (tid == 0) {
        // ---- dtype-agnostic target fetch (int32 vs int64 buffer) ----
        bool is_i64 = true;
        #pragma unroll 1
        for (int k = 1; k < 64; k += 2) {
            if (__ldg(&target_raw[k]) != 0) { is_i64 = false; break; }
        }
        int tg;
        if (is_i64) tg = __ldg(&target_raw[2 * (int)row]);   // low word of int64
        else        tg = __ldg(&target_raw[(int)row]);
        if (tg < 0) tg = 0;
        if (tg >= V) tg = V - 1;   // defensive clamp: never fault

        float xt = __ldg(&xrow[tg]);
        // sum(p^alpha) = A / S^1.5 ; loss = (1 - sumPa)/0.75 + D/S - X[target]
        float sumPa = A / (S * sqrtf(S));
        out[row] = (1.0f - sumPa) / 0.75f + D / S - xt;
    }
}

extern "C" void kernel_launch(void* const* d_in, const int* in_sizes, int n_in,
                              void* d_out, int out_size)
{
    const float* X   = (const float*)d_in[0];
    const int*   tgt = (const int*)d_in[1];
    float*       out = (float*)d_out;
    const int B = out_size;   // 4096 rows

    bisection_loss_kernel<<<B, NT>>>(X, tgt, out);
}